// round 6
// baseline (speedup 1.0000x reference)
#include <cuda_runtime.h>

// Problem constants
#define TT   1024   // seq len
#define BB   1024   // batch
#define HH   64     // encoder hidden
#define NB   7      // batch elements per CTA
#define CTAS 147    // 147*7 = 1029 >= 1024
#define HP   68     // padded h stride (bank-spreads the b*HP term)

// ---------------------------------------------------------------------------
// helpers
// ---------------------------------------------------------------------------
__device__ __forceinline__ void ffma2(unsigned long long &d,
                                      unsigned long long a,
                                      unsigned long long b) {
    asm("fma.rn.f32x2 %0, %1, %2, %0;" : "+l"(d) : "l"(a), "l"(b));
}
__device__ __forceinline__ unsigned long long packf2(float lo, float hi) {
    unsigned long long r;
    asm("mov.b64 %0, {%1,%2};" : "=l"(r) : "f"(lo), "f"(hi));
    return r;
}
__device__ __forceinline__ float ex2f(float x) {
    float r; asm("ex2.approx.f32 %0, %1;" : "=f"(r) : "f"(x)); return r;
}
__device__ __forceinline__ float rcpf(float x) {
    float r; asm("rcp.approx.f32 %0, %1;" : "=f"(r) : "f"(x)); return r;
}

#define L2E      1.4426950408889634f
#define TWO_L2E  2.8853900817779268f

__device__ __forceinline__ float tanhx(float x) {      // rel err ~1e-7
    return fmaf(-2.0f, rcpf(1.0f + ex2f(TWO_L2E * x)), 1.0f);
}

// ---------------------------------------------------------------------------
// Fused encoder+decoder. 147 CTAs x 256 threads; CTA owns NB=7 batch chains.
//
// Balanced single-group layout (all 8 warps identical -> no warp ever runs
// solo on its SMSP):
//   w = tid>>5, l = tid&31, q = l>>2, g = l&3
//   j = 8*w + q   (hidden index; warp w owns j in [8w, 8w+8))
//   row = g*64 + j (all 4 gates of a j live in one lane quad)
// One gate row x 64 k of Whh per thread in regs (32 packed f32x2) -- zero
// weight replication (16K regs/SM total). Every warp processes ALL 7
// batches: per SMSP = 2 warps x 224 FFMA2 = 896-cyc FMA-pipe floor exactly.
//
// Epilogue: per batch 4x shfl.idx gathers (i,f,g,o) into every lane; the
// c/h update is OWNED by lane g == (b&3) (selects save the 4 acts into 2
// slots) so tanh(c) issues only 2x per warp per step (was 14x) -> MUFU pipe
// drops well under the matvec budget. Owner lane stores h.
// One __syncthreads per step; hs double-buffered, stride HP=68 (bank spread).
// Decoder (hidden=1) fused at the end.
// ---------------------------------------------------------------------------
__global__ void __launch_bounds__(256, 1) fused_kernel(
    const float* __restrict__ x,      // [T, B, 1]
    const float* __restrict__ Wih,    // [256, 1]
    const float* __restrict__ Whh,    // [256, 64]
    const float* __restrict__ bih,    // [256]
    const float* __restrict__ bhh,    // [256]
    const float* __restrict__ Wih_d,  // [4, 64]
    const float* __restrict__ Whh_d,  // [4, 1]
    const float* __restrict__ bih_d,  // [4]
    const float* __restrict__ bhh_d,  // [4]
    float* __restrict__ out)          // [T, B, 1]
{
    const int tid = threadIdx.x;
    const int w   = tid >> 5;
    const int l   = tid & 31;
    const int q   = l >> 2;
    const int g   = l & 3;
    const int j   = 8 * w + q;
    const int row = g * HH + j;
    const int qb  = q * 4;            // quad base lane
    const int b0  = blockIdx.x * NB;

    __shared__ __align__(16) float hs[2][NB][HP];  // double-buffered hidden
    __shared__ __align__(16) float xs[2][8];       // double-buffered x bcast

    // activation parametrization (g==2 is the tanh gate)
    const bool isTanh = (g == 2);
    const float s  = isTanh ? TWO_L2E : -L2E;      // folded into weights/bias
    const float Am = isTanh ? -2.0f : 1.0f;
    const float Bm = isTanh ?  1.0f : 0.0f;

    // my gate row of Whh, pre-scaled, packed over k (32 x f32x2)
    unsigned long long w2[32];
    {
        const float2* wp = (const float2*)(Whh + row * HH);
        #pragma unroll
        for (int i = 0; i < 32; i++) {
            float2 v = wp[i];
            w2[i] = packf2(v.x * s, v.y * s);
        }
    }
    const float be   = s * (bih[row] + bhh[row]);
    const float wihr = s * Wih[row];               // IN==1 rank-1 input term

    // init h = 0 (buffer 0) and x for t=0
    for (int i = tid; i < NB * HP; i += 256) ((float*)hs[0])[i] = 0.0f;
    if (tid < 8) {
        int gb = b0 + tid; if (gb > BB - 1) gb = BB - 1;
        xs[0][tid] = x[gb];
        xs[1][tid] = 0.0f;
    }
    float cc[2] = {0.0f, 0.0f};       // cell state for owned batches
    __syncthreads();

    for (int t = 0; t < TT; t++) {
        const float* __restrict__ hr = hs[t & 1][0];
        float* __restrict__       hw = hs[(t + 1) & 1][0];

        // x for this step (two LDS.128 of the broadcast buffer)
        float4 xlo = *(const float4*)&xs[t & 1][0];
        float4 xhi = *(const float4*)&xs[t & 1][4];
        float xb[7] = {xlo.x, xlo.y, xlo.z, xlo.w, xhi.x, xhi.y, xhi.z};

        // prefetch next step's x (hidden under the matvec)
        if ((tid < 8) && (t + 1 < TT)) {
            int gb = b0 + tid; if (gb > BB - 1) gb = BB - 1;
            xs[(t + 1) & 1][tid] = __ldg(&x[(t + 1) * BB + gb]);
        }

        // ---- accumulator init: bias + input term ----
        unsigned long long acc[NB];
        #pragma unroll
        for (int b = 0; b < NB; b++)
            acc[b] = packf2(fmaf(wihr, xb[b], be), 0.0f);

        // ---- matvec: all 7 batches, 7 interleaved FFMA2 chains ----
        #pragma unroll
        for (int kk = 0; kk < 16; kk++) {
            #pragma unroll
            for (int b = 0; b < NB; b++) {
                ulonglong2 h4 = ((const ulonglong2*)(hr + b * HP))[kk];
                ffma2(acc[b], w2[2 * kk],     h4.x);
                ffma2(acc[b], w2[2 * kk + 1], h4.y);
            }
        }

        // ---- activations: one per lane per batch ----
        float act[NB];
        #pragma unroll
        for (int b = 0; b < NB; b++) {
            float lo, hi;
            asm("mov.b64 {%0,%1}, %2;" : "=f"(lo), "=f"(hi) : "l"(acc[b]));
            act[b] = fmaf(Am, rcpf(1.0f + ex2f(lo + hi)), Bm);
        }

        // ---- gather gates per batch; owner lane (g == b&3) keeps them ----
        float aiq[2] = {0.0f, 0.0f}, afq[2] = {0.0f, 0.0f};
        float agq[2] = {0.0f, 0.0f}, aoq[2] = {0.0f, 0.0f};
        #pragma unroll
        for (int b = 0; b < NB; b++) {
            float ai = __shfl_sync(0xffffffffu, act[b], qb + 0);
            float af = __shfl_sync(0xffffffffu, act[b], qb + 1);
            float ag = __shfl_sync(0xffffffffu, act[b], qb + 2);
            float ao = __shfl_sync(0xffffffffu, act[b], qb + 3);
            if (g == (b & 3)) {                     // compile-time slot b>>2
                aiq[b >> 2] = ai; afq[b >> 2] = af;
                agq[b >> 2] = ag; aoq[b >> 2] = ao;
            }
        }

        // ---- c/h update: 2 owned batches per lane (g=3 owns 1) ----
        #pragma unroll
        for (int slot = 0; slot < 2; slot++) {
            int b = slot * 4 + g;
            cc[slot] = fmaf(afq[slot], cc[slot], aiq[slot] * agq[slot]);
            float hn = aoq[slot] * tanhx(cc[slot]);
            if (b < NB) hw[b * HP + j] = hn;
        }

        __syncthreads();
    }
    // final hidden state is in hs[0] (t=1023 wrote buffer (1024)&1 = 0)

    // ------------------- fused decoder (7 threads per CTA) -------------------
    if (tid < NB) {
        const int gb = b0 + tid;
        if (gb < BB) {
            const float* he = hs[0][tid];
            float z[4], wd[4];
            #pragma unroll
            for (int gg = 0; gg < 4; gg++) {
                float acc = bih_d[gg] + bhh_d[gg];
                const float* wr = Wih_d + gg * HH;
                #pragma unroll 8
                for (int k = 0; k < HH; k++) acc = fmaf(wr[k], he[k], acc);
                const float sd = (gg == 2) ? TWO_L2E : -L2E;
                z[gg]  = sd * acc;
                wd[gg] = sd * Whh_d[gg];
            }
            float h = 0.0f, c = 0.0f;
            float* op = out + gb;
            for (int t = 0; t < TT; t++) {
                float gi = fmaf(wd[0], h, z[0]);
                float gf = fmaf(wd[1], h, z[1]);
                float gg2 = fmaf(wd[2], h, z[2]);
                float go = fmaf(wd[3], h, z[3]);
                float ai = rcpf(1.0f + ex2f(gi));
                float af = rcpf(1.0f + ex2f(gf));
                float ag = fmaf(-2.0f, rcpf(1.0f + ex2f(gg2)), 1.0f);
                float ao = rcpf(1.0f + ex2f(go));
                c = fmaf(af, c, ai * ag);
                h = ao * tanhx(c);
                *op = h;
                op += BB;
            }
        }
    }
}

// ---------------------------------------------------------------------------
// launch
// ---------------------------------------------------------------------------
extern "C" void kernel_launch(void* const* d_in, const int* in_sizes, int n_in,
                              void* d_out, int out_size) {
    const float* x     = (const float*)d_in[0];
    const float* Wih_e = (const float*)d_in[1];
    const float* Whh_e = (const float*)d_in[2];
    const float* bih_e = (const float*)d_in[3];
    const float* bhh_e = (const float*)d_in[4];
    const float* Wih_d = (const float*)d_in[5];
    const float* Whh_d = (const float*)d_in[6];
    const float* bih_d = (const float*)d_in[7];
    const float* bhh_d = (const float*)d_in[8];
    float* out = (float*)d_out;

    fused_kernel<<<CTAS, 256>>>(x, Wih_e, Whh_e, bih_e, bhh_e,
                                Wih_d, Whh_d, bih_d, bhh_d, out);
}

// round 7
// speedup vs baseline: 1.0424x; 1.0424x over previous
#include <cuda_runtime.h>

// Problem constants
#define TT   1024   // seq len
#define BB   1024   // batch
#define HH   64     // encoder hidden
#define NB   4      // batch elements per CTA
#define CTAS 256    // 256*4 = 1024 exactly

// ---------------------------------------------------------------------------
// helpers
// ---------------------------------------------------------------------------
__device__ __forceinline__ void ffma2(unsigned long long &d,
                                      unsigned long long a,
                                      unsigned long long b) {
    asm("fma.rn.f32x2 %0, %1, %2, %0;" : "+l"(d) : "l"(a), "l"(b));
}
__device__ __forceinline__ unsigned long long packf2(float lo, float hi) {
    unsigned long long r;
    asm("mov.b64 %0, {%1,%2};" : "=l"(r) : "f"(lo), "f"(hi));
    return r;
}
__device__ __forceinline__ float ex2f(float x) {
    float r; asm("ex2.approx.f32 %0, %1;" : "=f"(r) : "f"(x)); return r;
}
__device__ __forceinline__ float rcpf(float x) {
    float r; asm("rcp.approx.f32 %0, %1;" : "=f"(r) : "f"(x)); return r;
}

#define L2E      1.4426950408889634f
#define TWO_L2E  2.8853900817779268f

__device__ __forceinline__ float tanhx(float x) {      // rel err ~1e-7
    return fmaf(-2.0f, rcpf(1.0f + ex2f(TWO_L2E * x)), 1.0f);
}

// ---------------------------------------------------------------------------
// Fused encoder+decoder. 256 CTAs x 128 threads, 2 CTAs/SM.
//
// Per CTA: NB=4 batch chains, 4 warps (1 per SMSP). The co-resident CTA on
// the same SM provides the second warp per SMSP; because the two CTAs sync
// independently (cheap 4-warp __syncthreads) they drift in phase, so one
// CTA's MUFU/shuffle epilogue hides under the other's FFMA2 matvec stream.
//
// Thread layout: j = tid>>1 (hidden index), half = tid&1
//   half0 -> gate rows (i,f) = (j, j+64); half1 -> (g,o) = (j+128, j+192)
// 2 gate rows of Whh per thread in regs (64 packed f32x2 = 128 regs; at 128
// threads the regfile allows ~255/thread, giving ptxas deep h-load buffers).
// Activation scale folded into weights/bias. Epilogue: butterfly shfl
// (lane^1) exchanges (i,f)<->(g,o); both halves update c (1 FMA); ONLY
// half0 computes tanh(c) and stores h (half1 never needs it -> -17% MUFU).
// One __syncthreads per step; hs double-buffered.
// x: one uniform LDG.128 (4 consecutive batches) per step, prefetched.
// Decoder (hidden=1) fused: 4 threads per CTA handle the CTA's own batches.
// ---------------------------------------------------------------------------
__global__ void __launch_bounds__(128, 2) fused_kernel(
    const float* __restrict__ x,      // [T, B, 1]
    const float* __restrict__ Wih,    // [256, 1]
    const float* __restrict__ Whh,    // [256, 64]
    const float* __restrict__ bih,    // [256]
    const float* __restrict__ bhh,    // [256]
    const float* __restrict__ Wih_d,  // [4, 64]
    const float* __restrict__ Whh_d,  // [4, 1]
    const float* __restrict__ bih_d,  // [4]
    const float* __restrict__ bhh_d,  // [4]
    float* __restrict__ out)          // [T, B, 1]
{
    const int tid  = threadIdx.x;
    const int j    = tid >> 1;            // 0..63
    const int half = tid & 1;
    const int r0   = half * 128 + j;      // i (half0) / g (half1)
    const int r1   = r0 + 64;             // f (half0) / o (half1)
    const int b0   = blockIdx.x * NB;     // exact: 256*4 = 1024

    __shared__ __align__(16) float hs[2][NB][HH];  // double-buffered hidden

    // activation parametrization (r0: sigmoid/tanh, r1: sigmoid)
    const float s0 = half ? TWO_L2E : -L2E;
    const float s1 = -L2E;
    const float A0 = half ? -2.0f : 1.0f;
    const float B0 = half ?  1.0f : 0.0f;

    // weights for my two gate rows, pre-scaled, packed over k
    unsigned long long w0[32], w1[32];
    {
        const float2* p0 = (const float2*)(Whh + r0 * HH);
        const float2* p1 = (const float2*)(Whh + r1 * HH);
        #pragma unroll
        for (int i = 0; i < 32; i++) {
            float2 v0 = p0[i], v1 = p1[i];
            w0[i] = packf2(v0.x * s0, v0.y * s0);
            w1[i] = packf2(v1.x * s1, v1.y * s1);
        }
    }
    const float be0  = s0 * (bih[r0] + bhh[r0]);
    const float be1  = s1 * (bih[r1] + bhh[r1]);
    const float wih0 = s0 * Wih[r0];
    const float wih1 = s1 * Wih[r1];

    // x row pointer (16B-aligned: b0 is a multiple of 4)
    const float4* xrow = (const float4*)(x + b0);

    // init h = 0 (buffer 0), first x
    for (int i = tid; i < NB * HH; i += 128) ((float*)hs[0])[i] = 0.0f;
    float4 xv = __ldg(xrow);                  // x at t=0 (uniform)
    float cc[4] = {0.0f, 0.0f, 0.0f, 0.0f};
    __syncthreads();

    for (int t = 0; t < TT; t++) {
        const float* __restrict__ hr = hs[t & 1][0];
        float* __restrict__       hw = hs[(t + 1) & 1][0];

        // accumulator init: bias + input term (this step's x)
        const float xb[4] = {xv.x, xv.y, xv.z, xv.w};
        unsigned long long a0[4], a1[4];
        #pragma unroll
        for (int bi = 0; bi < 4; bi++) {
            a0[bi] = packf2(fmaf(wih0, xb[bi], be0), 0.0f);
            a1[bi] = packf2(fmaf(wih1, xb[bi], be1), 0.0f);
        }

        // prefetch next step's x (one uniform LDG.128, hidden under matvec)
        if (t + 1 < TT) xv = __ldg(xrow + (t + 1) * (BB / 4));

        // ---- matvec: 4 batches, 8 interleaved FFMA2 chains ----
        #pragma unroll
        for (int kk = 0; kk < 16; kk++) {
            #pragma unroll
            for (int bi = 0; bi < 4; bi++) {
                ulonglong2 h4 = ((const ulonglong2*)(hr + bi * HH))[kk];
                ffma2(a0[bi], w0[2 * kk],     h4.x);
                ffma2(a0[bi], w0[2 * kk + 1], h4.y);
                ffma2(a1[bi], w1[2 * kk],     h4.x);
                ffma2(a1[bi], w1[2 * kk + 1], h4.y);
            }
        }

        // ---- epilogue: activations + butterfly + c/h update ----
        #pragma unroll
        for (int bi = 0; bi < 4; bi++) {
            float l0, h0, l1, h1;
            asm("mov.b64 {%0,%1}, %2;" : "=f"(l0), "=f"(h0) : "l"(a0[bi]));
            asm("mov.b64 {%0,%1}, %2;" : "=f"(l1), "=f"(h1) : "l"(a1[bi]));
            float act0 = fmaf(A0, rcpf(1.0f + ex2f(l0 + h0)), B0);
            float act1 = rcpf(1.0f + ex2f(l1 + h1));

            float p0v = __shfl_xor_sync(0xffffffffu, act0, 1);
            float p1v = __shfl_xor_sync(0xffffffffu, act1, 1);
            float ai = half ? p0v  : act0;
            float af = half ? p1v  : act1;
            float ag = half ? act0 : p0v;
            float ao = half ? act1 : p1v;

            cc[bi] = fmaf(af, cc[bi], ai * ag);
            if (!half) {                       // only half0 needs h
                float hn = ao * tanhx(cc[bi]);
                hw[bi * HH + j] = hn;
            }
        }

        __syncthreads();
    }
    // final hidden state is in hs[0] (t=1023 wrote buffer (1024)&1 = 0)

    // ------------------- fused decoder (4 threads per CTA) -------------------
    if (tid < NB) {
        const float* he = hs[0][tid];
        float z[4], wd[4];
        #pragma unroll
        for (int g = 0; g < 4; g++) {
            float acc = bih_d[g] + bhh_d[g];
            const float* wr = Wih_d + g * HH;
            #pragma unroll 8
            for (int k = 0; k < HH; k++) acc = fmaf(wr[k], he[k], acc);
            const float s = (g == 2) ? TWO_L2E : -L2E;
            z[g]  = s * acc;
            wd[g] = s * Whh_d[g];
        }
        float h = 0.0f, c = 0.0f;
        float* op = out + b0 + tid;
        for (int t = 0; t < TT; t++) {
            float gi = fmaf(wd[0], h, z[0]);
            float gf = fmaf(wd[1], h, z[1]);
            float gg = fmaf(wd[2], h, z[2]);
            float go = fmaf(wd[3], h, z[3]);
            float ai = rcpf(1.0f + ex2f(gi));
            float af = rcpf(1.0f + ex2f(gf));
            float ag = fmaf(-2.0f, rcpf(1.0f + ex2f(gg)), 1.0f);
            float ao = rcpf(1.0f + ex2f(go));
            c = fmaf(af, c, ai * ag);
            h = ao * tanhx(c);
            *op = h;
            op += BB;
        }
    }
}

// ---------------------------------------------------------------------------
// launch
// ---------------------------------------------------------------------------
extern "C" void kernel_launch(void* const* d_in, const int* in_sizes, int n_in,
                              void* d_out, int out_size) {
    const float* x     = (const float*)d_in[0];
    const float* Wih_e = (const float*)d_in[1];
    const float* Whh_e = (const float*)d_in[2];
    const float* bih_e = (const float*)d_in[3];
    const float* bhh_e = (const float*)d_in[4];
    const float* Wih_d = (const float*)d_in[5];
    const float* Whh_d = (const float*)d_in[6];
    const float* bih_d = (const float*)d_in[7];
    const float* bhh_d = (const float*)d_in[8];
    float* out = (float*)d_out;

    fused_kernel<<<CTAS, 128>>>(x, Wih_e, Whh_e, bih_e, bhh_e,
                                Wih_d, Whh_d, bih_d, bhh_d, out);
}